// round 1
// baseline (speedup 1.0000x reference)
#include <cuda_runtime.h>
#include <math.h>

#define D_MODEL 1024
#define NHEAD   16
#define HEAD_DIM 64
#define B_SZ    4
#define L_SEQ   4096
#define M_ROWS  (B_SZ * L_SEQ)       // 16384
#define CHUNK   128
#define NCHUNK  (L_SEQ / CHUNK)      // 32
#define LN_EPS  1e-5f

// ---------------- scratch (device globals; no cudaMalloc allowed) ------------
__device__ float g_q[M_ROWS * D_MODEL];
__device__ float g_v[M_ROWS * D_MODEL];   // becomes state after scan (in place)
__device__ float g_g[M_ROWS * D_MODEL];
__device__ float g_y[M_ROWS * D_MODEL];
__device__ float g_carry[B_SZ * NHEAD * NCHUNK * HEAD_DIM];
__device__ float g_P[B_SZ * NHEAD * NCHUNK * HEAD_DIM];

// ---------------- fp32 SGEMM: C[M,N] = A[M,K] * B[N,K]^T  (both K-major) -----
// 128x128 tile, BK=8, 256 threads, 8x8 per thread.
#define BM 128
#define BN 128
#define BK 8

__global__ __launch_bounds__(256) void sgemm_nt(
    const float* __restrict__ A, const float* __restrict__ Bm,
    float* __restrict__ C, int M, int N, int K)
{
    __shared__ float As[BK][BM];
    __shared__ float Bs[BK][BN];

    const int tid = threadIdx.x;
    const int bm = blockIdx.y * BM;
    const int bn = blockIdx.x * BN;

    const int lrow = tid >> 1;          // 0..127
    const int lk4  = (tid & 1) * 4;     // 0 or 4

    const int tx = tid & 15;            // 0..15 -> N direction
    const int ty = tid >> 4;            // 0..15 -> M direction

    const float* Aptr = A + (size_t)(bm + lrow) * K + lk4;
    const float* Bptr = Bm + (size_t)(bn + lrow) * K + lk4;

    float acc[8][8];
#pragma unroll
    for (int i = 0; i < 8; i++)
#pragma unroll
        for (int j = 0; j < 8; j++) acc[i][j] = 0.f;

    for (int k0 = 0; k0 < K; k0 += BK) {
        float4 av = *(const float4*)(Aptr + k0);
        float4 bv = *(const float4*)(Bptr + k0);
        As[lk4 + 0][lrow] = av.x;
        As[lk4 + 1][lrow] = av.y;
        As[lk4 + 2][lrow] = av.z;
        As[lk4 + 3][lrow] = av.w;
        Bs[lk4 + 0][lrow] = bv.x;
        Bs[lk4 + 1][lrow] = bv.y;
        Bs[lk4 + 2][lrow] = bv.z;
        Bs[lk4 + 3][lrow] = bv.w;
        __syncthreads();

#pragma unroll
        for (int k = 0; k < BK; k++) {
            float4 a0 = *(const float4*)&As[k][ty * 8];
            float4 a1 = *(const float4*)&As[k][ty * 8 + 4];
            float4 b0 = *(const float4*)&Bs[k][tx * 8];
            float4 b1 = *(const float4*)&Bs[k][tx * 8 + 4];
            float a[8] = {a0.x, a0.y, a0.z, a0.w, a1.x, a1.y, a1.z, a1.w};
            float b[8] = {b0.x, b0.y, b0.z, b0.w, b1.x, b1.y, b1.z, b1.w};
#pragma unroll
            for (int i = 0; i < 8; i++)
#pragma unroll
                for (int j = 0; j < 8; j++)
                    acc[i][j] = fmaf(a[i], b[j], acc[i][j]);
        }
        __syncthreads();
    }

#pragma unroll
    for (int i = 0; i < 8; i++) {
        float* crow = C + (size_t)(bm + ty * 8 + i) * N + bn + tx * 8;
        float4 o0 = {acc[i][0], acc[i][1], acc[i][2], acc[i][3]};
        float4 o1 = {acc[i][4], acc[i][5], acc[i][6], acc[i][7]};
        *(float4*)(crow) = o0;
        *(float4*)(crow + 4) = o1;
    }
}

// ---------------- retention scan: local chunk scan (in place on g_v) ---------
__global__ void scan_local(const float* __restrict__ beta)
{
    const int blk = blockIdx.x;
    const int c = blk % NCHUNK;
    const int h = (blk / NCHUNK) % NHEAD;
    const int b = blk / (NCHUNK * NHEAD);
    const int dh = threadIdx.x;

    const float lam = 1.f / (1.f + expf(-beta[h]));

    size_t base = ((size_t)(b * L_SEQ + c * CHUNK)) * D_MODEL + h * HEAD_DIM + dh;
    float s = 0.f;
#pragma unroll 4
    for (int t = 0; t < CHUNK; t++) {
        size_t o = base + (size_t)t * D_MODEL;
        float vv = g_v[o];
        s = fmaf(lam, s, vv);
        g_v[o] = s;
    }
    g_carry[((b * NHEAD + h) * NCHUNK + c) * HEAD_DIM + dh] = s;
}

// ---------------- carry prefix across chunks (exact for any lambda) ----------
__global__ void scan_prefix(const float* __restrict__ beta)
{
    int idx = blockIdx.x * blockDim.x + threadIdx.x;
    if (idx >= B_SZ * NHEAD * HEAD_DIM) return;
    const int dh = idx % HEAD_DIM;
    const int h = (idx / HEAD_DIM) % NHEAD;
    const int b = idx / (HEAD_DIM * NHEAD);

    const float lam = 1.f / (1.f + expf(-beta[h]));
    const float lamC = powf(lam, (float)CHUNK);

    float P = 0.f;
    for (int c = 0; c < NCHUNK; c++) {
        int o = ((b * NHEAD + h) * NCHUNK + c) * HEAD_DIM + dh;
        g_P[o] = P;                      // state at end of previous chunk
        P = fmaf(lamC, P, g_carry[o]);
    }
}

// ---------------- fused: y = LN(q * state) * silu(gate) ----------------------
// one block per token, 256 threads, 4 elements each (D=1024)
__global__ __launch_bounds__(256) void ln_gate_kernel(
    const float* __restrict__ beta,
    const float* __restrict__ gamma,
    const float* __restrict__ lnb)
{
    const int token = blockIdx.x;
    const int b = token / L_SEQ;
    const int t = token % L_SEQ;
    const int c = t / CHUNK;
    const int j = t % CHUNK;
    const int tid = threadIdx.x;
    const int lane = tid & 31;
    const int w = tid >> 5;

    __shared__ float lampj[NHEAD];
    __shared__ float rs[8], rq[8];

    if (tid < NHEAD) {
        float lam = 1.f / (1.f + expf(-beta[tid]));
        lampj[tid] = powf(lam, (float)(j + 1));
    }
    __syncthreads();

    float z[4];
    float lsum = 0.f, lsq = 0.f;
#pragma unroll
    for (int i = 0; i < 4; i++) {
        int d = tid + i * 256;
        int h = d >> 6, dh = d & 63;
        size_t o = (size_t)token * D_MODEL + d;
        float st = g_v[o] + lampj[h] * g_P[((b * NHEAD + h) * NCHUNK + c) * HEAD_DIM + dh];
        float zz = g_q[o] * st;
        z[i] = zz;
        lsum += zz;
        lsq = fmaf(zz, zz, lsq);
    }

#pragma unroll
    for (int off = 16; off; off >>= 1) {
        lsum += __shfl_xor_sync(0xffffffffu, lsum, off);
        lsq  += __shfl_xor_sync(0xffffffffu, lsq, off);
    }
    if (lane == 0) { rs[w] = lsum; rq[w] = lsq; }
    __syncthreads();
    if (tid == 0) {
        float s = 0.f, s2 = 0.f;
#pragma unroll
        for (int i = 0; i < 8; i++) { s += rs[i]; s2 += rq[i]; }
        rs[0] = s; rq[0] = s2;
    }
    __syncthreads();

    const float inv = 1.f / (float)D_MODEL;
    float mu = rs[0] * inv;
    float var = rq[0] * inv - mu * mu;
    float r = rsqrtf(var + LN_EPS);

#pragma unroll
    for (int i = 0; i < 4; i++) {
        int d = tid + i * 256;
        size_t o = (size_t)token * D_MODEL + d;
        float yv = (z[i] - mu) * r * gamma[d] + lnb[d];
        float gg = g_g[o];
        yv *= gg / (1.f + expf(-gg));
        g_y[o] = yv;
    }
}

// ---------------- launch ------------------------------------------------------
extern "C" void kernel_launch(void* const* d_in, const int* in_sizes, int n_in,
                              void* d_out, int out_size)
{
    const float* x     = (const float*)d_in[0];
    const float* Wq    = (const float*)d_in[1];
    const float* Wv    = (const float*)d_in[2];
    const float* Wg    = (const float*)d_in[3];
    const float* Wo    = (const float*)d_in[4];
    const float* beta  = (const float*)d_in[5];
    const float* gamma = (const float*)d_in[6];
    const float* lnb   = (const float*)d_in[7];
    float* out = (float*)d_out;

    float *qp, *vp, *gp, *yp;
    cudaGetSymbolAddress((void**)&qp, g_q);
    cudaGetSymbolAddress((void**)&vp, g_v);
    cudaGetSymbolAddress((void**)&gp, g_g);
    cudaGetSymbolAddress((void**)&yp, g_y);

    const int M = M_ROWS, N = D_MODEL, K = D_MODEL;
    dim3 ggrid(N / BN, M / BM);

    sgemm_nt<<<ggrid, 256>>>(x, Wq, qp, M, N, K);
    sgemm_nt<<<ggrid, 256>>>(x, Wv, vp, M, N, K);
    sgemm_nt<<<ggrid, 256>>>(x, Wg, gp, M, N, K);

    scan_local<<<B_SZ * NHEAD * NCHUNK, HEAD_DIM>>>(beta);
    scan_prefix<<<(B_SZ * NHEAD * HEAD_DIM + 255) / 256, 256>>>(beta);

    ln_gate_kernel<<<M_ROWS, 256>>>(beta, gamma, lnb);

    sgemm_nt<<<ggrid, 256>>>(yp, Wo, out, M, N, K);
}

// round 3
// speedup vs baseline: 2.6051x; 2.6051x over previous
#include <cuda_runtime.h>
#include <cuda_bf16.h>
#include <math.h>
#include <stdint.h>

#define D_MODEL 1024
#define NHEAD   16
#define HEAD_DIM 64
#define B_SZ    4
#define L_SEQ   4096
#define M_ROWS  (B_SZ * L_SEQ)       // 16384
#define CHUNK   128
#define NCHUNK  (L_SEQ / CHUNK)      // 32
#define LN_EPS  1e-5f

// GEMM tiling
#define TM 128
#define TN 128
#define TK 64                         // bf16 per k-tile (128 B/row)
#define STAGES 4
#define A_STG_BYTES 16384             // 128 rows * 128 B
#define STAGE_BYTES 32768             // A + B
#define NKT 48                        // 3 phases * 16 k-tiles (K=1024 / 64)
#define GEMM_SMEM_SZ (STAGES * STAGE_BYTES)   // 131072

// ---------------- scratch (device globals) -----------------------------------
__device__ __nv_bfloat16 g_xs[2u * M_ROWS * D_MODEL];       // x hi | x lo
__device__ __nv_bfloat16 g_ys[2u * M_ROWS * D_MODEL];       // y hi | y lo
__device__ __nv_bfloat16 g_ws[4u * 2u * D_MODEL * D_MODEL]; // per weight: hi | lo
__device__ float g_q[M_ROWS * D_MODEL];
__device__ float g_v[M_ROWS * D_MODEL];
__device__ float g_g[M_ROWS * D_MODEL];
__device__ float g_carry[B_SZ * NHEAD * NCHUNK * HEAD_DIM];
__device__ float g_P[B_SZ * NHEAD * NCHUNK * HEAD_DIM];

// ---------------- PTX helpers ------------------------------------------------
#define CP16(dst, src) \
    asm volatile("cp.async.cg.shared.global [%0], [%1], 16;" :: "r"(dst), "l"(src))
#define CP_COMMIT() asm volatile("cp.async.commit_group;" ::: "memory")
#define CP_WAIT2()  asm volatile("cp.async.wait_group 2;" ::: "memory")

#define LDSM4(r0, r1, r2, r3, addr) \
    asm volatile("ldmatrix.sync.aligned.m8n8.x4.shared.b16 {%0,%1,%2,%3}, [%4];" \
        : "=r"(r0), "=r"(r1), "=r"(r2), "=r"(r3) : "r"(addr))

#define MMA16816(d, a, b0, b1) \
    asm volatile("mma.sync.aligned.m16n8k16.row.col.f32.bf16.bf16.f32 " \
        "{%0,%1,%2,%3}, {%4,%5,%6,%7}, {%8,%9}, {%0,%1,%2,%3};" \
        : "+f"((d)[0]), "+f"((d)[1]), "+f"((d)[2]), "+f"((d)[3]) \
        : "r"((a)[0]), "r"((a)[1]), "r"((a)[2]), "r"((a)[3]), "r"(b0), "r"(b1))

__device__ __forceinline__ uint32_t swz(uint32_t off) {
    return off ^ ((off >> 3) & 0x70);
}

// ---------------- split fp32 -> bf16 hi/lo -----------------------------------
__global__ __launch_bounds__(256) void split_kernel(
    const float* __restrict__ in, __nv_bfloat16* __restrict__ out, int n)
{
    int i = (blockIdx.x * 256 + threadIdx.x) * 4;
    if (i >= n) return;
    float4 v = *(const float4*)(in + i);
    __nv_bfloat16 h0 = __float2bfloat16_rn(v.x);
    __nv_bfloat16 h1 = __float2bfloat16_rn(v.y);
    __nv_bfloat16 h2 = __float2bfloat16_rn(v.z);
    __nv_bfloat16 h3 = __float2bfloat16_rn(v.w);
    __nv_bfloat16 l0 = __float2bfloat16_rn(v.x - __bfloat162float(h0));
    __nv_bfloat16 l1 = __float2bfloat16_rn(v.y - __bfloat162float(h1));
    __nv_bfloat16 l2 = __float2bfloat16_rn(v.z - __bfloat162float(h2));
    __nv_bfloat16 l3 = __float2bfloat16_rn(v.w - __bfloat162float(h3));
    __nv_bfloat162* oh = (__nv_bfloat162*)(out + i);
    oh[0] = __nv_bfloat162(h0, h1); oh[1] = __nv_bfloat162(h2, h3);
    __nv_bfloat162* ol = (__nv_bfloat162*)(out + n + i);
    ol[0] = __nv_bfloat162(l0, l1); ol[1] = __nv_bfloat162(l2, l3);
}

// ---------------- bf16x3 HMMA GEMM: C[16384,1024] = A*B^T ---------------------
// A': [hi(M_ROWS) | lo(M_ROWS)] x 1024, B': [hi(1024) | lo(1024)] x 1024
// phases over kt: 0 -> Ahi*Bhi, 1 -> Alo*Bhi, 2 -> Ahi*Blo
__device__ __forceinline__ void load_tile(
    const __nv_bfloat16* __restrict__ A, const __nv_bfloat16* __restrict__ B,
    int bm, int bn, int kt, uint32_t stg, int tid)
{
    const int phase = kt >> 4;
    const int kl = kt & 15;
    const size_t kcol = (size_t)kl * TK;
    const size_t arow0 = (size_t)bm + (phase == 1 ? (size_t)M_ROWS : 0);
    const size_t brow0 = (size_t)bn + (phase == 2 ? (size_t)D_MODEL : 0);
#pragma unroll
    for (int i = 0; i < 8; i++) {
        int c = tid + i * 256;                  // 0..2047
        int row = (c >> 3) & 127;
        int seg = c & 7;
        bool isA = (c < 1024);
        const __nv_bfloat16* src = isA
            ? (A + (arow0 + row) * D_MODEL + kcol + seg * 8)
            : (B + (brow0 + row) * D_MODEL + kcol + seg * 8);
        uint32_t off = (uint32_t)(row * 128 + seg * 16);
        uint32_t dst = stg + (isA ? 0u : (uint32_t)A_STG_BYTES) + swz(off);
        CP16(dst, src);
    }
}

__global__ __launch_bounds__(256, 1)
void gemm_bf16x3(const __nv_bfloat16* __restrict__ A,
                 const __nv_bfloat16* __restrict__ B,
                 float* __restrict__ C)
{
    extern __shared__ char smem[];
    const uint32_t sbase = (uint32_t)__cvta_generic_to_shared(smem);
    const int tid = threadIdx.x;
    const int wid = tid >> 5;
    const int lane = tid & 31;
    const int bm = blockIdx.y * TM;
    const int bn = blockIdx.x * TN;

    const int wm = (wid >> 2) * 64;   // warp m offset within tile (0 or 64)
    const int wn = (wid & 3) * 32;    // warp n offset within tile

    float acc[4][4][4];
#pragma unroll
    for (int i = 0; i < 4; i++)
#pragma unroll
        for (int j = 0; j < 4; j++)
#pragma unroll
            for (int r = 0; r < 4; r++) acc[i][j][r] = 0.f;

    // prologue: prefetch 3 tiles
    load_tile(A, B, bm, bn, 0, sbase + 0 * STAGE_BYTES, tid); CP_COMMIT();
    load_tile(A, B, bm, bn, 1, sbase + 1 * STAGE_BYTES, tid); CP_COMMIT();
    load_tile(A, B, bm, bn, 2, sbase + 2 * STAGE_BYTES, tid); CP_COMMIT();

    // precomputed ldmatrix lane addressing (row/col within tile)
    const int lrow = lane & 15;                 // row within 16-row group
    const int lcol = (lane >> 4) << 4;          // 0 or 16 bytes (k halves)

    for (int kt = 0; kt < NKT; kt++) {
        const uint32_t sa = sbase + (kt % STAGES) * STAGE_BYTES;
        const uint32_t sb = sa + A_STG_BYTES;
        CP_WAIT2();
        __syncthreads();

        // prefetch kt+3 into the stage freed last iteration
        if (kt + 3 < NKT)
            load_tile(A, B, bm, bn, kt + 3, sbase + ((kt + 3) % STAGES) * STAGE_BYTES, tid);
        CP_COMMIT();

#pragma unroll
        for (int kk = 0; kk < 4; kk++) {        // 4 x k16 within BK=64
            const uint32_t colb = kk * 32 + lcol;
            uint32_t a[4][4];
#pragma unroll
            for (int i = 0; i < 4; i++) {
                uint32_t off = (uint32_t)((wm + i * 16 + lrow) * 128) + colb;
                LDSM4(a[i][0], a[i][1], a[i][2], a[i][3], sa + swz(off));
            }
            uint32_t br[2][4];
#pragma unroll
            for (int j2 = 0; j2 < 2; j2++) {
                uint32_t off = (uint32_t)((wn + j2 * 16 + lrow) * 128) + colb;
                LDSM4(br[j2][0], br[j2][1], br[j2][2], br[j2][3], sb + swz(off));
            }
#pragma unroll
            for (int i = 0; i < 4; i++)
#pragma unroll
                for (int j = 0; j < 4; j++) {
                    const int j2 = j >> 1, jj = j & 1;
                    MMA16816(acc[i][j], a[i], br[j2][jj], br[j2][2 + jj]);
                }
        }
    }

    // epilogue: direct global stores (f32)
    const int r0 = lane >> 2;
    const int c0 = (lane & 3) * 2;
#pragma unroll
    for (int i = 0; i < 4; i++) {
#pragma unroll
        for (int j = 0; j < 4; j++) {
            float* cp0 = C + (size_t)(bm + wm + i * 16 + r0) * D_MODEL + bn + wn + j * 8 + c0;
            float* cp1 = cp0 + 8 * D_MODEL;
            *(float2*)cp0 = make_float2(acc[i][j][0], acc[i][j][1]);
            *(float2*)cp1 = make_float2(acc[i][j][2], acc[i][j][3]);
        }
    }
}

// ---------------- retention scan ----------------------------------------------
__global__ void scan_local(const float* __restrict__ beta)
{
    const int blk = blockIdx.x;
    const int c = blk % NCHUNK;
    const int h = (blk / NCHUNK) % NHEAD;
    const int b = blk / (NCHUNK * NHEAD);
    const int dh = threadIdx.x;

    const float lam = 1.f / (1.f + expf(-beta[h]));

    size_t base = ((size_t)(b * L_SEQ + c * CHUNK)) * D_MODEL + h * HEAD_DIM + dh;
    float s = 0.f;
#pragma unroll 4
    for (int t = 0; t < CHUNK; t++) {
        size_t o = base + (size_t)t * D_MODEL;
        float vv = g_v[o];
        s = fmaf(lam, s, vv);
        g_v[o] = s;
    }
    g_carry[((b * NHEAD + h) * NCHUNK + c) * HEAD_DIM + dh] = s;
}

__global__ void scan_prefix(const float* __restrict__ beta)
{
    int idx = blockIdx.x * blockDim.x + threadIdx.x;
    if (idx >= B_SZ * NHEAD * HEAD_DIM) return;
    const int dh = idx % HEAD_DIM;
    const int h = (idx / HEAD_DIM) % NHEAD;
    const int b = idx / (HEAD_DIM * NHEAD);

    const float lam = 1.f / (1.f + expf(-beta[h]));
    const float lamC = powf(lam, (float)CHUNK);

    float P = 0.f;
    for (int c = 0; c < NCHUNK; c++) {
        int o = ((b * NHEAD + h) * NCHUNK + c) * HEAD_DIM + dh;
        g_P[o] = P;
        P = fmaf(lamC, P, g_carry[o]);
    }
}

// ---------------- fused: y = LN(q*state)*silu(gate) -> bf16 hi/lo --------------
__global__ __launch_bounds__(256) void ln_gate_kernel(
    const float* __restrict__ beta,
    const float* __restrict__ gamma,
    const float* __restrict__ lnb)
{
    const int token = blockIdx.x;
    const int b = token / L_SEQ;
    const int t = token % L_SEQ;
    const int c = t / CHUNK;
    const int j = t % CHUNK;
    const int tid = threadIdx.x;
    const int lane = tid & 31;
    const int w = tid >> 5;

    __shared__ float lampj[NHEAD];
    __shared__ float rs[8], rq[8];

    if (tid < NHEAD) {
        float lam = 1.f / (1.f + expf(-beta[tid]));
        lampj[tid] = powf(lam, (float)(j + 1));
    }
    __syncthreads();

    float z[4];
    float lsum = 0.f, lsq = 0.f;
#pragma unroll
    for (int i = 0; i < 4; i++) {
        int d = tid + i * 256;
        int h = d >> 6, dh = d & 63;
        size_t o = (size_t)token * D_MODEL + d;
        float st = g_v[o] + lampj[h] * g_P[((b * NHEAD + h) * NCHUNK + c) * HEAD_DIM + dh];
        float zz = g_q[o] * st;
        z[i] = zz;
        lsum += zz;
        lsq = fmaf(zz, zz, lsq);
    }

#pragma unroll
    for (int off = 16; off; off >>= 1) {
        lsum += __shfl_xor_sync(0xffffffffu, lsum, off);
        lsq  += __shfl_xor_sync(0xffffffffu, lsq, off);
    }
    if (lane == 0) { rs[w] = lsum; rq[w] = lsq; }
    __syncthreads();
    if (tid == 0) {
        float s = 0.f, s2 = 0.f;
#pragma unroll
        for (int i = 0; i < 8; i++) { s += rs[i]; s2 += rq[i]; }
        rs[0] = s; rq[0] = s2;
    }
    __syncthreads();

    const float inv = 1.f / (float)D_MODEL;
    float mu = rs[0] * inv;
    float var = rq[0] * inv - mu * mu;
    float r = rsqrtf(var + LN_EPS);

#pragma unroll
    for (int i = 0; i < 4; i++) {
        int d = tid + i * 256;
        size_t o = (size_t)token * D_MODEL + d;
        float yv = (z[i] - mu) * r * gamma[d] + lnb[d];
        float gg = g_g[o];
        yv *= gg / (1.f + expf(-gg));
        __nv_bfloat16 h = __float2bfloat16_rn(yv);
        __nv_bfloat16 l = __float2bfloat16_rn(yv - __bfloat162float(h));
        g_ys[o] = h;
        g_ys[o + (size_t)M_ROWS * D_MODEL] = l;
    }
}

// ---------------- launch ------------------------------------------------------
extern "C" void kernel_launch(void* const* d_in, const int* in_sizes, int n_in,
                              void* d_out, int out_size)
{
    const float* x     = (const float*)d_in[0];
    const float* Wq    = (const float*)d_in[1];
    const float* Wv    = (const float*)d_in[2];
    const float* Wg    = (const float*)d_in[3];
    const float* Wo    = (const float*)d_in[4];
    const float* beta  = (const float*)d_in[5];
    const float* gamma = (const float*)d_in[6];
    const float* lnb   = (const float*)d_in[7];
    float* out = (float*)d_out;

    __nv_bfloat16 *xs, *ys, *ws;
    float *qp, *vp, *gp;
    cudaGetSymbolAddress((void**)&xs, g_xs);
    cudaGetSymbolAddress((void**)&ys, g_ys);
    cudaGetSymbolAddress((void**)&ws, g_ws);
    cudaGetSymbolAddress((void**)&qp, g_q);
    cudaGetSymbolAddress((void**)&vp, g_v);
    cudaGetSymbolAddress((void**)&gp, g_g);

    cudaFuncSetAttribute(gemm_bf16x3, cudaFuncAttributeMaxDynamicSharedMemorySize,
                         GEMM_SMEM_SZ);

    const int NX = M_ROWS * D_MODEL;        // 16777216
    const int NW = D_MODEL * D_MODEL;       // 1048576
    const size_t WSEG = 2u * (size_t)NW;

    split_kernel<<<NX / 1024, 256>>>(x, xs, NX);
    split_kernel<<<NW / 1024, 256>>>(Wq, ws + 0 * WSEG, NW);
    split_kernel<<<NW / 1024, 256>>>(Wv, ws + 1 * WSEG, NW);
    split_kernel<<<NW / 1024, 256>>>(Wg, ws + 2 * WSEG, NW);
    split_kernel<<<NW / 1024, 256>>>(Wo, ws + 3 * WSEG, NW);

    dim3 ggrid(D_MODEL / TN, M_ROWS / TM);  // (8, 128)
    gemm_bf16x3<<<ggrid, 256, GEMM_SMEM_SZ>>>(xs, ws + 0 * WSEG, qp);
    gemm_bf16x3<<<ggrid, 256, GEMM_SMEM_SZ>>>(xs, ws + 1 * WSEG, vp);
    gemm_bf16x3<<<ggrid, 256, GEMM_SMEM_SZ>>>(xs, ws + 2 * WSEG, gp);

    scan_local<<<B_SZ * NHEAD * NCHUNK, HEAD_DIM>>>(beta);
    scan_prefix<<<(B_SZ * NHEAD * HEAD_DIM + 255) / 256, 256>>>(beta);

    ln_gate_kernel<<<M_ROWS, 256>>>(beta, gamma, lnb);

    gemm_bf16x3<<<ggrid, 256, GEMM_SMEM_SZ>>>(ys, ws + 3 * WSEG, out);
}

// round 4
// speedup vs baseline: 3.0885x; 1.1856x over previous
#include <cuda_runtime.h>
#include <cuda_bf16.h>
#include <math.h>
#include <stdint.h>

#define D_MODEL 1024
#define NHEAD   16
#define HEAD_DIM 64
#define B_SZ    4
#define L_SEQ   4096
#define M_ROWS  (B_SZ * L_SEQ)       // 16384
#define CHUNK   128
#define NCHUNK  (L_SEQ / CHUNK)      // 32
#define LN_EPS  1e-5f

// GEMM tiling
#define TM 128
#define TN 128
#define TK 64                         // bf16 per k-tile (128 B/row)
#define STAGES 3
#define A_STG_BYTES 16384             // 128 rows * 128 B
#define STAGE_BYTES 32768             // A + B
#define NKT 48                        // 3 phases * 16 k-tiles (K=1024 / 64)
#define GEMM_SMEM_SZ (STAGES * STAGE_BYTES)   // 98304

// ---------------- scratch (device globals) -----------------------------------
__device__ __nv_bfloat16 g_xs[2u * M_ROWS * D_MODEL];       // x hi | x lo
__device__ __nv_bfloat16 g_ys[2u * M_ROWS * D_MODEL];       // y hi | y lo
__device__ __nv_bfloat16 g_ws[4u * 2u * D_MODEL * D_MODEL]; // per weight: hi | lo
__device__ float g_q[M_ROWS * D_MODEL];
__device__ float g_v[M_ROWS * D_MODEL];
__device__ float g_g[M_ROWS * D_MODEL];
__device__ float g_carry[B_SZ * NHEAD * NCHUNK * HEAD_DIM];
__device__ float g_P[B_SZ * NHEAD * NCHUNK * HEAD_DIM];

// ---------------- PTX helpers ------------------------------------------------
#define CP16(dst, src) \
    asm volatile("cp.async.cg.shared.global [%0], [%1], 16;" :: "r"(dst), "l"(src))
#define CP_COMMIT() asm volatile("cp.async.commit_group;" ::: "memory")
#define CP_WAIT1()  asm volatile("cp.async.wait_group 1;" ::: "memory")

#define LDSM4(r0, r1, r2, r3, addr) \
    asm volatile("ldmatrix.sync.aligned.m8n8.x4.shared.b16 {%0,%1,%2,%3}, [%4];" \
        : "=r"(r0), "=r"(r1), "=r"(r2), "=r"(r3) : "r"(addr))

#define MMA16816(d, a, b0, b1) \
    asm volatile("mma.sync.aligned.m16n8k16.row.col.f32.bf16.bf16.f32 " \
        "{%0,%1,%2,%3}, {%4,%5,%6,%7}, {%8,%9}, {%0,%1,%2,%3};" \
        : "+f"((d)[0]), "+f"((d)[1]), "+f"((d)[2]), "+f"((d)[3]) \
        : "r"((a)[0]), "r"((a)[1]), "r"((a)[2]), "r"((a)[3]), "r"(b0), "r"(b1))

__device__ __forceinline__ uint32_t swz(uint32_t off) {
    return off ^ ((off >> 3) & 0x70);
}

// ---------------- split fp32 -> bf16 hi/lo -----------------------------------
__global__ __launch_bounds__(256) void split_kernel(
    const float* __restrict__ in, __nv_bfloat16* __restrict__ out, int n)
{
    int i = (blockIdx.x * 256 + threadIdx.x) * 4;
    if (i >= n) return;
    float4 v = *(const float4*)(in + i);
    __nv_bfloat16 h0 = __float2bfloat16_rn(v.x);
    __nv_bfloat16 h1 = __float2bfloat16_rn(v.y);
    __nv_bfloat16 h2 = __float2bfloat16_rn(v.z);
    __nv_bfloat16 h3 = __float2bfloat16_rn(v.w);
    __nv_bfloat16 l0 = __float2bfloat16_rn(v.x - __bfloat162float(h0));
    __nv_bfloat16 l1 = __float2bfloat16_rn(v.y - __bfloat162float(h1));
    __nv_bfloat16 l2 = __float2bfloat16_rn(v.z - __bfloat162float(h2));
    __nv_bfloat16 l3 = __float2bfloat16_rn(v.w - __bfloat162float(h3));
    __nv_bfloat162* oh = (__nv_bfloat162*)(out + i);
    oh[0] = __nv_bfloat162(h0, h1); oh[1] = __nv_bfloat162(h2, h3);
    __nv_bfloat162* ol = (__nv_bfloat162*)(out + n + i);
    ol[0] = __nv_bfloat162(l0, l1); ol[1] = __nv_bfloat162(l2, l3);
}

// ---------------- bf16x3 HMMA GEMM: C[16384,1024] = A*B^T ---------------------
// A': [hi(M_ROWS) | lo(M_ROWS)] x 1024, B': [hi(1024) | lo(1024)] x 1024
// phases over kt: 0 -> Ahi*Bhi, 1 -> Alo*Bhi, 2 -> Ahi*Blo
__device__ __forceinline__ void load_tile(
    const __nv_bfloat16* __restrict__ A, const __nv_bfloat16* __restrict__ B,
    int bm, int bn, int kt, uint32_t stg, int tid)
{
    const int phase = kt >> 4;
    const int kl = kt & 15;
    const size_t kcol = (size_t)kl * TK;
    const size_t arow0 = (size_t)bm + (phase == 1 ? (size_t)M_ROWS : 0);
    const size_t brow0 = (size_t)bn + (phase == 2 ? (size_t)D_MODEL : 0);
#pragma unroll
    for (int i = 0; i < 8; i++) {
        int c = tid + i * 256;                  // 0..2047
        int row = (c >> 3) & 127;
        int seg = c & 7;
        bool isA = (c < 1024);
        const __nv_bfloat16* src = isA
            ? (A + (arow0 + row) * D_MODEL + kcol + seg * 8)
            : (B + (brow0 + row) * D_MODEL + kcol + seg * 8);
        uint32_t off = (uint32_t)(row * 128 + seg * 16);
        uint32_t dst = stg + (isA ? 0u : (uint32_t)A_STG_BYTES) + swz(off);
        CP16(dst, src);
    }
}

__global__ __launch_bounds__(256, 2)
void gemm_bf16x3(const __nv_bfloat16* __restrict__ A,
                 const __nv_bfloat16* __restrict__ B,
                 float* __restrict__ C)
{
    extern __shared__ char smem[];
    const uint32_t sbase = (uint32_t)__cvta_generic_to_shared(smem);
    const int tid = threadIdx.x;
    const int wid = tid >> 5;
    const int lane = tid & 31;
    const int bm = blockIdx.y * TM;
    const int bn = blockIdx.x * TN;

    const int wm = (wid >> 2) * 64;   // warp m offset within tile (0 or 64)
    const int wn = (wid & 3) * 32;    // warp n offset within tile

    float acc[4][4][4];
#pragma unroll
    for (int i = 0; i < 4; i++)
#pragma unroll
        for (int j = 0; j < 4; j++)
#pragma unroll
            for (int r = 0; r < 4; r++) acc[i][j][r] = 0.f;

    // prologue: prefetch 2 tiles
    load_tile(A, B, bm, bn, 0, sbase + 0 * STAGE_BYTES, tid); CP_COMMIT();
    load_tile(A, B, bm, bn, 1, sbase + 1 * STAGE_BYTES, tid); CP_COMMIT();

    // ldmatrix lane addressing
    const int lrow = lane & 15;                 // row within 16-row group
    const int lcol = (lane >> 4) << 4;          // 0 or 16 bytes (k halves)

    for (int kt = 0; kt < NKT; kt++) {
        const uint32_t sa = sbase + (kt % STAGES) * STAGE_BYTES;
        const uint32_t sb = sa + A_STG_BYTES;
        CP_WAIT1();
        __syncthreads();

        // prefetch kt+2 into the stage freed at the end of kt-1
        if (kt + 2 < NKT)
            load_tile(A, B, bm, bn, kt + 2, sbase + ((kt + 2) % STAGES) * STAGE_BYTES, tid);
        CP_COMMIT();

#pragma unroll
        for (int kk = 0; kk < 4; kk++) {        // 4 x k16 within BK=64
            const uint32_t colb = kk * 32 + lcol;
            uint32_t a[4][4];
#pragma unroll
            for (int i = 0; i < 4; i++) {
                uint32_t off = (uint32_t)((wm + i * 16 + lrow) * 128) + colb;
                LDSM4(a[i][0], a[i][1], a[i][2], a[i][3], sa + swz(off));
            }
            uint32_t br[2][4];
#pragma unroll
            for (int j2 = 0; j2 < 2; j2++) {
                uint32_t off = (uint32_t)((wn + j2 * 16 + lrow) * 128) + colb;
                LDSM4(br[j2][0], br[j2][1], br[j2][2], br[j2][3], sb + swz(off));
            }
#pragma unroll
            for (int i = 0; i < 4; i++)
#pragma unroll
                for (int j = 0; j < 4; j++) {
                    const int j2 = j >> 1, jj = j & 1;
                    MMA16816(acc[i][j], a[i], br[j2][jj], br[j2][2 + jj]);
                }
        }
    }

    // epilogue: direct global stores (f32)
    const int r0 = lane >> 2;
    const int c0 = (lane & 3) * 2;
#pragma unroll
    for (int i = 0; i < 4; i++) {
#pragma unroll
        for (int j = 0; j < 4; j++) {
            float* cp0 = C + (size_t)(bm + wm + i * 16 + r0) * D_MODEL + bn + wn + j * 8 + c0;
            float* cp1 = cp0 + 8 * D_MODEL;
            *(float2*)cp0 = make_float2(acc[i][j][0], acc[i][j][1]);
            *(float2*)cp1 = make_float2(acc[i][j][2], acc[i][j][3]);
        }
    }
}

// ---------------- retention scan ----------------------------------------------
__global__ void scan_local(const float* __restrict__ beta)
{
    const int blk = blockIdx.x;
    const int c = blk % NCHUNK;
    const int h = (blk / NCHUNK) % NHEAD;
    const int b = blk / (NCHUNK * NHEAD);
    const int dh = threadIdx.x;

    const float lam = 1.f / (1.f + expf(-beta[h]));

    size_t base = ((size_t)(b * L_SEQ + c * CHUNK)) * D_MODEL + h * HEAD_DIM + dh;
    float s = 0.f;
#pragma unroll 4
    for (int t = 0; t < CHUNK; t++) {
        size_t o = base + (size_t)t * D_MODEL;
        float vv = g_v[o];
        s = fmaf(lam, s, vv);
        g_v[o] = s;
    }
    g_carry[((b * NHEAD + h) * NCHUNK + c) * HEAD_DIM + dh] = s;
}

__global__ void scan_prefix(const float* __restrict__ beta)
{
    int idx = blockIdx.x * blockDim.x + threadIdx.x;
    if (idx >= B_SZ * NHEAD * HEAD_DIM) return;
    const int dh = idx % HEAD_DIM;
    const int h = (idx / HEAD_DIM) % NHEAD;
    const int b = idx / (HEAD_DIM * NHEAD);

    const float lam = 1.f / (1.f + expf(-beta[h]));
    const float lamC = powf(lam, (float)CHUNK);

    float P = 0.f;
    for (int c = 0; c < NCHUNK; c++) {
        int o = ((b * NHEAD + h) * NCHUNK + c) * HEAD_DIM + dh;
        g_P[o] = P;
        P = fmaf(lamC, P, g_carry[o]);
    }
}

// ---------------- fused: y = LN(q*state)*silu(gate) -> bf16 hi/lo --------------
__global__ __launch_bounds__(256) void ln_gate_kernel(
    const float* __restrict__ beta,
    const float* __restrict__ gamma,
    const float* __restrict__ lnb)
{
    const int token = blockIdx.x;
    const int b = token / L_SEQ;
    const int t = token % L_SEQ;
    const int c = t / CHUNK;
    const int j = t % CHUNK;
    const int tid = threadIdx.x;
    const int lane = tid & 31;
    const int w = tid >> 5;

    __shared__ float lampj[NHEAD];
    __shared__ float rs[8], rq[8];

    if (tid < NHEAD) {
        float lam = 1.f / (1.f + expf(-beta[tid]));
        lampj[tid] = powf(lam, (float)(j + 1));
    }
    __syncthreads();

    float z[4];
    float lsum = 0.f, lsq = 0.f;
#pragma unroll
    for (int i = 0; i < 4; i++) {
        int d = tid + i * 256;
        int h = d >> 6, dh = d & 63;
        size_t o = (size_t)token * D_MODEL + d;
        float st = g_v[o] + lampj[h] * g_P[((b * NHEAD + h) * NCHUNK + c) * HEAD_DIM + dh];
        float zz = g_q[o] * st;
        z[i] = zz;
        lsum += zz;
        lsq = fmaf(zz, zz, lsq);
    }

#pragma unroll
    for (int off = 16; off; off >>= 1) {
        lsum += __shfl_xor_sync(0xffffffffu, lsum, off);
        lsq  += __shfl_xor_sync(0xffffffffu, lsq, off);
    }
    if (lane == 0) { rs[w] = lsum; rq[w] = lsq; }
    __syncthreads();
    if (tid == 0) {
        float s = 0.f, s2 = 0.f;
#pragma unroll
        for (int i = 0; i < 8; i++) { s += rs[i]; s2 += rq[i]; }
        rs[0] = s; rq[0] = s2;
    }
    __syncthreads();

    const float inv = 1.f / (float)D_MODEL;
    float mu = rs[0] * inv;
    float var = rq[0] * inv - mu * mu;
    float r = rsqrtf(var + LN_EPS);

#pragma unroll
    for (int i = 0; i < 4; i++) {
        int d = tid + i * 256;
        size_t o = (size_t)token * D_MODEL + d;
        float yv = (z[i] - mu) * r * gamma[d] + lnb[d];
        float gg = g_g[o];
        yv *= gg / (1.f + expf(-gg));
        __nv_bfloat16 h = __float2bfloat16_rn(yv);
        __nv_bfloat16 l = __float2bfloat16_rn(yv - __bfloat162float(h));
        g_ys[o] = h;
        g_ys[o + (size_t)M_ROWS * D_MODEL] = l;
    }
}

// ---------------- launch ------------------------------------------------------
extern "C" void kernel_launch(void* const* d_in, const int* in_sizes, int n_in,
                              void* d_out, int out_size)
{
    const float* x     = (const float*)d_in[0];
    const float* Wq    = (const float*)d_in[1];
    const float* Wv    = (const float*)d_in[2];
    const float* Wg    = (const float*)d_in[3];
    const float* Wo    = (const float*)d_in[4];
    const float* beta  = (const float*)d_in[5];
    const float* gamma = (const float*)d_in[6];
    const float* lnb   = (const float*)d_in[7];
    float* out = (float*)d_out;

    __nv_bfloat16 *xs, *ys, *ws;
    float *qp, *vp, *gp;
    cudaGetSymbolAddress((void**)&xs, g_xs);
    cudaGetSymbolAddress((void**)&ys, g_ys);
    cudaGetSymbolAddress((void**)&ws, g_ws);
    cudaGetSymbolAddress((void**)&qp, g_q);
    cudaGetSymbolAddress((void**)&vp, g_v);
    cudaGetSymbolAddress((void**)&gp, g_g);

    cudaFuncSetAttribute(gemm_bf16x3, cudaFuncAttributeMaxDynamicSharedMemorySize,
                         GEMM_SMEM_SZ);

    const int NX = M_ROWS * D_MODEL;        // 16777216
    const int NW = D_MODEL * D_MODEL;       // 1048576
    const size_t WSEG = 2u * (size_t)NW;

    split_kernel<<<NX / 1024, 256>>>(x, xs, NX);
    split_kernel<<<NW / 1024, 256>>>(Wq, ws + 0 * WSEG, NW);
    split_kernel<<<NW / 1024, 256>>>(Wv, ws + 1 * WSEG, NW);
    split_kernel<<<NW / 1024, 256>>>(Wg, ws + 2 * WSEG, NW);
    split_kernel<<<NW / 1024, 256>>>(Wo, ws + 3 * WSEG, NW);

    dim3 ggrid(D_MODEL / TN, M_ROWS / TM);  // (8, 128)
    gemm_bf16x3<<<ggrid, 256, GEMM_SMEM_SZ>>>(xs, ws + 0 * WSEG, qp);
    gemm_bf16x3<<<ggrid, 256, GEMM_SMEM_SZ>>>(xs, ws + 1 * WSEG, vp);
    gemm_bf16x3<<<ggrid, 256, GEMM_SMEM_SZ>>>(xs, ws + 2 * WSEG, gp);

    scan_local<<<B_SZ * NHEAD * NCHUNK, HEAD_DIM>>>(beta);
    scan_prefix<<<(B_SZ * NHEAD * HEAD_DIM + 255) / 256, 256>>>(beta);

    ln_gate_kernel<<<M_ROWS, 256>>>(beta, gamma, lnb);

    gemm_bf16x3<<<ggrid, 256, GEMM_SMEM_SZ>>>(ys, ws + 3 * WSEG, out);
}